// round 7
// baseline (speedup 1.0000x reference)
#include <cuda_runtime.h>
#include <math.h>
#include <stdint.h>

#define MARGIN            0.3f
#define CLST_SCALE        0.8f
#define SEP_SCALE         0.08f
#define DIV_SCALE         0.01f
#define CONTRASTIVE_SCALE 0.1f

#define MAXC 1024
#define MAXD 1024
#define MAXR 32
#define TPB  128    // 4 warps per block
#define NV4  8      // max float4 vectors per lane in fast path (CP <= 1024)

struct Scratch {
    float cls_n[MAXC];
    float cls_sum[MAXC];
    float sep_sum[MAXC];
    float svec[MAXD];
    float div_sum;
    float ndv;
    float diag;
    unsigned int counter;
};
__device__ Scratch g;

__device__ __forceinline__ float inff() { return __int_as_float(0x7f800000); }

// Elementwise routing for the (rare) vectors overlapping the own-class window.
__device__ __forceinline__ void accum4(int base, float4 v, int lo, int hi,
                                       float& om, float& tm) {
    {   bool own = (base + 0 >= lo) && (base + 0 < hi);
        if (own) om = fmaxf(om, v.x); else tm = fmaxf(tm, v.x); }
    {   bool own = (base + 1 >= lo) && (base + 1 < hi);
        if (own) om = fmaxf(om, v.y); else tm = fmaxf(tm, v.y); }
    {   bool own = (base + 2 >= lo) && (base + 2 < hi);
        if (own) om = fmaxf(om, v.z); else tm = fmaxf(tm, v.z); }
    {   bool own = (base + 3 >= lo) && (base + 3 < hi);
        if (own) om = fmaxf(om, v.w); else tm = fmaxf(tm, v.w); }
}

// Load one row (predicated, -inf sentinel so compute is unconditional).
__device__ __forceinline__ void load_row(float4* v, const float4* s4,
                                         int lane, int n4) {
    const float NI = -inff();
    #pragma unroll
    for (int k = 0; k < NV4; k++) {
        int i4 = lane + 32 * k;
        v[k] = make_float4(NI, NI, NI, NI);
        if (i4 < n4) v[k] = s4[i4];
    }
}

// Vector-granular max routing over one register-resident row.
__device__ __forceinline__ void row_max(const float4* v, int lane,
                                        int lo, int hi,
                                        float& om, float& tm) {
    #pragma unroll
    for (int k = 0; k < NV4; k++) {
        int base = (lane + 32 * k) * 4;
        float4 x = v[k];
        bool overlap = (base + 3 >= lo) && (base < hi);
        if (!overlap) {
            float m4 = fmaxf(fmaxf(x.x, x.y), fmaxf(x.z, x.w));
            tm = fmaxf(tm, m4);
        } else {
            accum4(base, x, lo, hi, om, tm);
        }
    }
}

__global__ void __launch_bounds__(TPB)
fused_kernel(const float* __restrict__ sims,
             const int*   __restrict__ labels,
             const float* __restrict__ protos,
             const int*   __restrict__ pidx,
             const unsigned char* __restrict__ mask,
             float* __restrict__ out,
             int B, int C, int P, int T, int D, int NMIN, int fast_ok) {
    const int tid  = threadIdx.x;
    const int warp = tid >> 5, lane = tid & 31;
    const int nwarp = TPB >> 5;

    if ((int)blockIdx.x < C) {
        // =================== proto block for class c =======================
        int bad = 0;
        {
            const int* mi = (const int*)mask;
            const int n = T >> 2;
            for (int i = tid; i < n; i += TPB) {
                int v = mi[i];
                bad |= (v != 0 && v != 1);
            }
        }
        const int byte_mode = __syncthreads_or(bad);

        __shared__ float s_inv[MAXR];
        __shared__ float s_rn2[MAXR];
        __shared__ int   s_rvalid[MAXR];
        __shared__ float s_pair;

        const int c = blockIdx.x;
        int rs = pidx[2 * c];
        int re = (c + 1 < C) ? pidx[2 * (c + 1)] : T;
        if (re > T) re = T;
        if (rs < 0) rs = 0;
        int nr = re - rs;
        if (nr > MAXR) nr = MAXR;
        if (nr < 0) nr = 0;

        if (tid == 0) s_pair = 0.f;
        const bool d4ok = ((D & 3) == 0);
        const int  D4   = D >> 2;
        const float4* p4 = (const float4*)protos;

        // per-row inverse norms (vectorized)
        for (int r = warp; r < nr; r += nwarp) {
            float ss = 0.f;
            if (d4ok) {
                const float4* src = p4 + (size_t)(rs + r) * D4;
                for (int d = lane; d < D4; d += 32) {
                    float4 x = src[d];
                    ss += x.x * x.x + x.y * x.y + x.z * x.z + x.w * x.w;
                }
            } else {
                const float* src = protos + (size_t)(rs + r) * D;
                for (int d = lane; d < D; d += 32) { float v = src[d]; ss += v * v; }
            }
            #pragma unroll
            for (int o = 16; o; o >>= 1) ss += __shfl_xor_sync(0xFFFFFFFFu, ss, o);
            float inv = 1.0f / fmaxf(sqrtf(ss), 1e-12f);
            if (lane == 0) {
                s_inv[r] = inv;
                s_rn2[r] = ss * inv * inv;
                int t = rs + r;
                int v = byte_mode ? (int)mask[t] : ((const int*)mask)[t];
                s_rvalid[r] = (v != 0);
            }
        }
        __syncthreads();

        // valid-row normalized vector sum -> g.svec ; diag -> g.diag
        if (d4ok) {
            for (int d = tid; d < D4; d += TPB) {
                float4 acc = make_float4(0.f, 0.f, 0.f, 0.f);
                for (int r = 0; r < nr; r++) {
                    if (s_rvalid[r]) {
                        float4 x = p4[(size_t)(rs + r) * D4 + d];
                        float iv = s_inv[r];
                        acc.x += x.x * iv; acc.y += x.y * iv;
                        acc.z += x.z * iv; acc.w += x.w * iv;
                    }
                }
                atomicAdd(&g.svec[4 * d + 0], acc.x);
                atomicAdd(&g.svec[4 * d + 1], acc.y);
                atomicAdd(&g.svec[4 * d + 2], acc.z);
                atomicAdd(&g.svec[4 * d + 3], acc.w);
            }
        } else {
            for (int d = tid; d < D; d += TPB) {
                float s = 0.f;
                for (int r = 0; r < nr; r++)
                    if (s_rvalid[r])
                        s += protos[(size_t)(rs + r) * D + d] * s_inv[r];
                atomicAdd(&g.svec[d], s);
            }
        }
        if (tid == 0) {
            float ds = 0.f;
            for (int r = 0; r < nr; r++) if (s_rvalid[r]) ds += s_rn2[r];
            atomicAdd(&g.diag, ds);
        }

        // same-class off-diagonal relu pair sum (x2 for both orders)
        const int npr = nr * (nr - 1) / 2;
        float local = 0.f;
        for (int k = warp; k < npr; k += nwarp) {
            int i = 0, rem = k;
            while (rem >= nr - 1 - i) { rem -= nr - 1 - i; i++; }
            int j = i + 1 + rem;
            float dot = 0.f;
            if (d4ok) {
                const float4* ri = p4 + (size_t)(rs + i) * D4;
                const float4* rj = p4 + (size_t)(rs + j) * D4;
                for (int d = lane; d < D4; d += 32) {
                    float4 a = ri[d], b = rj[d];
                    dot += a.x * b.x + a.y * b.y + a.z * b.z + a.w * b.w;
                }
            } else {
                const float* ri = protos + (size_t)(rs + i) * D;
                const float* rj = protos + (size_t)(rs + j) * D;
                for (int d = lane; d < D; d += 32) dot += ri[d] * rj[d];
            }
            #pragma unroll
            for (int o = 16; o; o >>= 1) dot += __shfl_xor_sync(0xFFFFFFFFu, dot, o);
            if (lane == 0)
                local += 2.0f * fmaxf(dot * s_inv[i] * s_inv[j] - 0.5f, 0.f);
        }
        if (lane == 0 && local != 0.f) atomicAdd(&s_pair, local);
        __syncthreads();

        if (tid == 0) {
            int cnt = pidx[2 * c + 1] - pidx[2 * c];
            if (cnt > 1) {
                float npf = (float)cnt * (float)(cnt - 1);
                atomicAdd(&g.div_sum, s_pair / fmaxf(npf, 1.0f));
                atomicAdd(&g.ndv, 1.0f);
            }
        }
        __syncthreads();
    } else {
        // =================== streaming min warps (pipelined) ===============
        const int CP = C * P;
        const int gw = ((int)blockIdx.x - C) * nwarp + warp;
        const int stride = NMIN * nwarp;

        if (fast_ok) {
            const int n4 = CP >> 2;
            float4 v[NV4];
            int b = gw;
            int lbl = 0;
            if (b < B) {
                load_row(v, (const float4*)(sims + (size_t)b * CP), lane, n4);
                lbl = labels[b];
            }
            while (b < B) {
                const int bn = b + stride;
                float4 w[NV4];
                int lbln = 0;
                if (bn < B) {          // prefetch next row while v computes
                    load_row(w, (const float4*)(sims + (size_t)bn * CP), lane, n4);
                    lbln = labels[bn];
                }

                const int lo = lbl * P, hi = lo + P;
                float ownmax = -inff(), othermax = -inff();
                row_max(v, lane, lo, hi, ownmax, othermax);
                #pragma unroll
                for (int o = 16; o; o >>= 1) {
                    ownmax   = fmaxf(ownmax,   __shfl_xor_sync(0xFFFFFFFFu, ownmax,   o));
                    othermax = fmaxf(othermax, __shfl_xor_sync(0xFFFFFFFFu, othermax, o));
                }
                if (lane == 0) {
                    float own   = 1.0f - ownmax;
                    float other = 1.0f - othermax;
                    float sep   = fmaxf(MARGIN - other, 0.0f);
                    atomicAdd(&g.cls_n[lbl],   1.0f);
                    atomicAdd(&g.cls_sum[lbl], own);
                    atomicAdd(&g.sep_sum[lbl], sep);
                }
                #pragma unroll
                for (int k = 0; k < NV4; k++) v[k] = w[k];
                lbl = lbln;
                b = bn;
            }
        } else {
            // general fallback: per-class scalar walk straight from global
            for (int b = gw; b < B; b += stride) {
                const float* src = sims + (size_t)b * CP;
                const int lbl = labels[b];
                float ownmax = -inff(), othermax = -inff();
                for (int c = lane; c < C; c += 32) {
                    int cnt = pidx[2 * c + 1] - pidx[2 * c];
                    if (cnt > P) cnt = P;
                    float m = -inff();
                    const float* pr = src + c * P;
                    for (int p = 0; p < cnt; p++) m = fmaxf(m, pr[p]);
                    if (c == lbl) ownmax = m;
                    else          othermax = fmaxf(othermax, m);
                }
                #pragma unroll
                for (int o = 16; o; o >>= 1) {
                    ownmax   = fmaxf(ownmax,   __shfl_xor_sync(0xFFFFFFFFu, ownmax,   o));
                    othermax = fmaxf(othermax, __shfl_xor_sync(0xFFFFFFFFu, othermax, o));
                }
                if (lane == 0) {
                    float own   = 1.0f - ownmax;
                    float other = 1.0f - othermax;
                    float sep   = fmaxf(MARGIN - other, 0.0f);
                    atomicAdd(&g.cls_n[lbl],   1.0f);
                    atomicAdd(&g.cls_sum[lbl], own);
                    atomicAdd(&g.sep_sum[lbl], sep);
                }
            }
        }
        __syncthreads();
    }

    // =================== last-block finalize ===============================
    __threadfence();
    __shared__ unsigned int s_ord;
    if (tid == 0) s_ord = atomicAdd(&g.counter, 1u);
    __syncthreads();
    if (s_ord != (unsigned)(C + NMIN - 1)) return;
    __threadfence();

    int bad2 = 0;
    {
        const int* mi = (const int*)mask;
        const int n = T >> 2;
        for (int i = tid; i < n; i += TPB) {
            int v = mi[i];
            bad2 |= (v != 0 && v != 1);
        }
    }
    const int byte_mode = __syncthreads_or(bad2);

    __shared__ float red[TPB];
    float ca = 0.f, sa = 0.f, nv = 0.f;
    for (int c = tid; c < C; c += TPB) {
        float n = g.cls_n[c];
        if (n > 0.f) {
            nv += 1.f;
            float nm = fmaxf(n, 1.f);
            ca += (1.0f / sqrtf(n + 1e-6f)) * (g.cls_sum[c] / nm);
            sa += g.sep_sum[c] / nm;
        }
    }
    float sn = 0.f;
    for (int d = tid; d < D; d += TPB) { float v = g.svec[d]; sn += v * v; }
    float vc = 0.f;
    for (int t = tid; t < T; t += TPB) {
        int v = byte_mode ? (int)mask[t] : ((const int*)mask)[t];
        vc += (v != 0) ? 1.f : 0.f;
    }

    float vals[5] = {ca, sa, nv, sn, vc};
    #pragma unroll
    for (int k = 0; k < 5; k++) {
        red[tid] = vals[k];
        __syncthreads();
        for (int s = TPB >> 1; s; s >>= 1) {
            if (tid < s) red[tid] += red[tid + s];
            __syncthreads();
        }
        vals[k] = red[0];
        __syncthreads();
    }

    if (tid == 0) {
        float nvalid  = fmaxf(vals[2], 1.f);
        float cluster = vals[0] / nvalid * CLST_SCALE;
        float sep     = vals[1] / nvalid * SEP_SCALE;
        float divl    = g.div_sum / fmaxf(g.ndv, 1.f) * DIV_SCALE;
        float V       = vals[4];
        float nvp     = fmaxf(V * V - V, 1.f);
        float contr   = (vals[3] - g.diag) / nvp * CONTRASTIVE_SCALE;
        out[0] = cluster;
        out[1] = sep;
        out[2] = divl;
        out[3] = contr;
        out[4] = cluster + sep + divl + contr;
    }
}

extern "C" void kernel_launch(void* const* d_in, const int* in_sizes, int n_in,
                              void* d_out, int out_size) {
    const float* sims   = (const float*)d_in[0];
    const int*   labels = (const int*)  d_in[1];
    const float* protos = (const float*)d_in[2];
    const int*   pidx   = (const int*)  d_in[3];
    const unsigned char* mask = (const unsigned char*)d_in[4];

    const int B = in_sizes[1];
    const int C = in_sizes[3] / 2;
    const int T = in_sizes[4];
    const int D = in_sizes[2] / T;
    const int P = in_sizes[0] / (B * C);
    float* out = (float*)d_out;

    void* gp = nullptr;
    cudaGetSymbolAddress(&gp, g);
    cudaMemsetAsync(gp, 0, sizeof(Scratch), 0);

    const int CP = C * P;
    // Fast path: vectorizable row, fits the NV4 register budget.
    const int fast_ok = (((CP & 3) == 0) && (CP <= NV4 * 32 * 4)) ? 1 : 0;

    // Each min warp handles exactly 2 samples (pipelined back-to-back).
    int NMIN = (B + 7) / 8;                 // B / (2 rows * 4 warps)
    if (NMIN < 148) NMIN = 148;
    fused_kernel<<<C + NMIN, TPB, 0>>>(sims, labels, protos, pidx, mask,
                                       out, B, C, P, T, D, NMIN, fast_ok);
}

// round 8
// speedup vs baseline: 1.0830x; 1.0830x over previous
#include <cuda_runtime.h>
#include <math.h>
#include <stdint.h>

#define MARGIN            0.3f
#define CLST_SCALE        0.8f
#define SEP_SCALE         0.08f
#define DIV_SCALE         0.01f
#define CONTRASTIVE_SCALE 0.1f

#define MAXC 1024
#define MAXD 1024
#define MAXR 32
#define TPB  128    // 4 warps per block

struct Scratch {
    float cls_n[MAXC];
    float cls_sum[MAXC];
    float sep_sum[MAXC];
    float svec[MAXD];
    float div_sum;
    float ndv;
    float diag;
    unsigned int counter;
};
__device__ Scratch g;

__device__ __forceinline__ float inff() { return __int_as_float(0x7f800000); }

// Load half a row (4 float4 per lane), -inf sentinel out of range.
template<int OFF>
__device__ __forceinline__ void loadH(float4* v, const float4* s4,
                                      int lane, int n4) {
    const float NI = -inff();
    #pragma unroll
    for (int k = 0; k < 4; k++) {
        int i = lane + 32 * (OFF + k);
        v[k] = make_float4(NI, NI, NI, NI);
        if (i < n4) v[k] = s4[i];
    }
}

// Max over half a row, excluding the aligned vector range [viL, viH].
template<int OFF>
__device__ __forceinline__ void reduceH(const float4* v, int lane,
                                        int viL, int viH, float& oth) {
    #pragma unroll
    for (int k = 0; k < 4; k++) {
        int vi = lane + 32 * (OFF + k);
        float4 x = v[k];
        float m4 = fmaxf(fmaxf(x.x, x.y), fmaxf(x.z, x.w));
        if (vi < viL || vi > viH) oth = fmaxf(oth, m4);
    }
}

__global__ void __launch_bounds__(TPB, 6)
fused_kernel(const float* __restrict__ sims,
             const int*   __restrict__ labels,
             const float* __restrict__ protos,
             const int*   __restrict__ pidx,
             const unsigned char* __restrict__ mask,
             float* __restrict__ out,
             int B, int C, int P, int T, int D, int NMIN, int fast_ok) {
    const int tid  = threadIdx.x;
    const int warp = tid >> 5, lane = tid & 31;
    const int nwarp = TPB >> 5;

    if ((int)blockIdx.x < C) {
        // =================== proto block for class c =======================
        int bad = 0;
        {
            const int* mi = (const int*)mask;
            const int n = T >> 2;
            for (int i = tid; i < n; i += TPB) {
                int v = mi[i];
                bad |= (v != 0 && v != 1);
            }
        }
        const int byte_mode = __syncthreads_or(bad);

        __shared__ float s_inv[MAXR];
        __shared__ float s_rn2[MAXR];
        __shared__ int   s_rvalid[MAXR];
        __shared__ float s_pair;

        const int c = blockIdx.x;
        int rs = pidx[2 * c];
        int re = (c + 1 < C) ? pidx[2 * (c + 1)] : T;
        if (re > T) re = T;
        if (rs < 0) rs = 0;
        int nr = re - rs;
        if (nr > MAXR) nr = MAXR;
        if (nr < 0) nr = 0;

        if (tid == 0) s_pair = 0.f;
        const bool d4ok = ((D & 3) == 0);
        const int  D4   = D >> 2;
        const float4* p4 = (const float4*)protos;

        for (int r = warp; r < nr; r += nwarp) {
            float ss = 0.f;
            if (d4ok) {
                const float4* src = p4 + (size_t)(rs + r) * D4;
                for (int d = lane; d < D4; d += 32) {
                    float4 x = src[d];
                    ss += x.x * x.x + x.y * x.y + x.z * x.z + x.w * x.w;
                }
            } else {
                const float* src = protos + (size_t)(rs + r) * D;
                for (int d = lane; d < D; d += 32) { float v = src[d]; ss += v * v; }
            }
            #pragma unroll
            for (int o = 16; o; o >>= 1) ss += __shfl_xor_sync(0xFFFFFFFFu, ss, o);
            float inv = 1.0f / fmaxf(sqrtf(ss), 1e-12f);
            if (lane == 0) {
                s_inv[r] = inv;
                s_rn2[r] = ss * inv * inv;
                int t = rs + r;
                int v = byte_mode ? (int)mask[t] : ((const int*)mask)[t];
                s_rvalid[r] = (v != 0);
            }
        }
        __syncthreads();

        if (d4ok) {
            for (int d = tid; d < D4; d += TPB) {
                float4 acc = make_float4(0.f, 0.f, 0.f, 0.f);
                for (int r = 0; r < nr; r++) {
                    if (s_rvalid[r]) {
                        float4 x = p4[(size_t)(rs + r) * D4 + d];
                        float iv = s_inv[r];
                        acc.x += x.x * iv; acc.y += x.y * iv;
                        acc.z += x.z * iv; acc.w += x.w * iv;
                    }
                }
                atomicAdd(&g.svec[4 * d + 0], acc.x);
                atomicAdd(&g.svec[4 * d + 1], acc.y);
                atomicAdd(&g.svec[4 * d + 2], acc.z);
                atomicAdd(&g.svec[4 * d + 3], acc.w);
            }
        } else {
            for (int d = tid; d < D; d += TPB) {
                float s = 0.f;
                for (int r = 0; r < nr; r++)
                    if (s_rvalid[r])
                        s += protos[(size_t)(rs + r) * D + d] * s_inv[r];
                atomicAdd(&g.svec[d], s);
            }
        }
        if (tid == 0) {
            float ds = 0.f;
            for (int r = 0; r < nr; r++) if (s_rvalid[r]) ds += s_rn2[r];
            atomicAdd(&g.diag, ds);
        }

        const int npr = nr * (nr - 1) / 2;
        float local = 0.f;
        for (int k = warp; k < npr; k += nwarp) {
            int i = 0, rem = k;
            while (rem >= nr - 1 - i) { rem -= nr - 1 - i; i++; }
            int j = i + 1 + rem;
            float dot = 0.f;
            if (d4ok) {
                const float4* ri = p4 + (size_t)(rs + i) * D4;
                const float4* rj = p4 + (size_t)(rs + j) * D4;
                for (int d = lane; d < D4; d += 32) {
                    float4 a = ri[d], b = rj[d];
                    dot += a.x * b.x + a.y * b.y + a.z * b.z + a.w * b.w;
                }
            } else {
                const float* ri = protos + (size_t)(rs + i) * D;
                const float* rj = protos + (size_t)(rs + j) * D;
                for (int d = lane; d < D; d += 32) dot += ri[d] * rj[d];
            }
            #pragma unroll
            for (int o = 16; o; o >>= 1) dot += __shfl_xor_sync(0xFFFFFFFFu, dot, o);
            if (lane == 0)
                local += 2.0f * fmaxf(dot * s_inv[i] * s_inv[j] - 0.5f, 0.f);
        }
        if (lane == 0 && local != 0.f) atomicAdd(&s_pair, local);
        __syncthreads();

        if (tid == 0) {
            int cnt = pidx[2 * c + 1] - pidx[2 * c];
            if (cnt > 1) {
                float npf = (float)cnt * (float)(cnt - 1);
                atomicAdd(&g.div_sum, s_pair / fmaxf(npf, 1.0f));
                atomicAdd(&g.ndv, 1.0f);
            }
        }
        __syncthreads();
    } else {
        // =================== streaming min warps ===========================
        const int CP = C * P;
        const int gw = ((int)blockIdx.x - C) * nwarp + warp;
        const int stride = NMIN * nwarp;

        // device-side check: fast path needs every class count >= P
        int okf = 1;
        for (int c = tid; c < C; c += TPB)
            okf &= ((pidx[2 * c + 1] - pidx[2 * c]) >= P);
        okf = __syncthreads_and(okf) & fast_ok;

        if (okf) {
            const int n4 = CP >> 2;
            int b = gw;
            if (b < B) {
                float4 A0[4], A1[4];
                const float4* s4 = (const float4*)(sims + (size_t)b * CP);
                int lbl = labels[b];
                loadH<0>(A0, s4, lane, n4);
                loadH<4>(A1, s4, lane, n4);
                int lo = lbl * P, hi = lo + P;
                int viL = lo >> 2, viH = (hi - 1) >> 2;
                int bidx = 4 * viL + lane;
                float bv = -inff();
                if (lane < 16 && bidx < CP)
                    bv = sims[(size_t)b * CP + bidx];

                while (true) {
                    const int bn = b + stride;
                    int lbln = 0;
                    if (bn < B) lbln = labels[bn];
                    const float4* s4n = (const float4*)(sims + (size_t)bn * CP);

                    float oth = -inff();
                    reduceH<0>(A0, lane, viL, viH, oth);
                    if (bn < B) loadH<0>(A0, s4n, lane, n4);   // prefetch next
                    reduceH<4>(A1, lane, viL, viH, oth);

                    // boundary region [4*viL, 4*viH+4): route to own / other
                    float own = -inff();
                    {
                        bool inwin = (bidx >= lo) && (bidx < hi);
                        if (inwin) own = bv;
                        else if (bidx <= 4 * viH + 3) oth = fmaxf(oth, bv);
                    }

                    int nlo = lbln * P, nhi = nlo + P;
                    int nviL = nlo >> 2, nviH = (nhi - 1) >> 2;
                    int nbidx = 4 * nviL + lane;
                    float nbv = -inff();
                    if (bn < B) {
                        loadH<4>(A1, s4n, lane, n4);           // prefetch next
                        if (lane < 16 && nbidx < CP)
                            nbv = sims[(size_t)bn * CP + nbidx];
                    }

                    #pragma unroll
                    for (int o = 16; o; o >>= 1) {
                        own = fmaxf(own, __shfl_xor_sync(0xFFFFFFFFu, own, o));
                        oth = fmaxf(oth, __shfl_xor_sync(0xFFFFFFFFu, oth, o));
                    }
                    if (lane == 0) {
                        float ownd  = 1.0f - own;
                        float sep   = fmaxf(MARGIN - (1.0f - oth), 0.0f);
                        atomicAdd(&g.cls_n[lbl],   1.0f);
                        atomicAdd(&g.cls_sum[lbl], ownd);
                        atomicAdd(&g.sep_sum[lbl], sep);
                    }
                    if (bn >= B) break;
                    b = bn; lbl = lbln;
                    lo = nlo; hi = nhi; viL = nviL; viH = nviH;
                    bidx = nbidx; bv = nbv;
                }
            }
        } else {
            // general fallback: per-class scalar walk straight from global
            for (int b = gw; b < B; b += stride) {
                const float* src = sims + (size_t)b * CP;
                const int lbl = labels[b];
                float ownmax = -inff(), othermax = -inff();
                for (int c = lane; c < C; c += 32) {
                    int cnt = pidx[2 * c + 1] - pidx[2 * c];
                    if (cnt > P) cnt = P;
                    float m = -inff();
                    const float* pr = src + c * P;
                    for (int p = 0; p < cnt; p++) m = fmaxf(m, pr[p]);
                    if (c == lbl) ownmax = m;
                    else          othermax = fmaxf(othermax, m);
                }
                #pragma unroll
                for (int o = 16; o; o >>= 1) {
                    ownmax   = fmaxf(ownmax,   __shfl_xor_sync(0xFFFFFFFFu, ownmax,   o));
                    othermax = fmaxf(othermax, __shfl_xor_sync(0xFFFFFFFFu, othermax, o));
                }
                if (lane == 0) {
                    float own   = 1.0f - ownmax;
                    float other = 1.0f - othermax;
                    float sep   = fmaxf(MARGIN - other, 0.0f);
                    atomicAdd(&g.cls_n[lbl],   1.0f);
                    atomicAdd(&g.cls_sum[lbl], own);
                    atomicAdd(&g.sep_sum[lbl], sep);
                }
            }
        }
        __syncthreads();
    }

    // =================== last-block finalize ===============================
    __threadfence();
    __shared__ unsigned int s_ord;
    if (tid == 0) s_ord = atomicAdd(&g.counter, 1u);
    __syncthreads();
    if (s_ord != (unsigned)(C + NMIN - 1)) return;
    __threadfence();

    int bad2 = 0;
    {
        const int* mi = (const int*)mask;
        const int n = T >> 2;
        for (int i = tid; i < n; i += TPB) {
            int v = mi[i];
            bad2 |= (v != 0 && v != 1);
        }
    }
    const int byte_mode = __syncthreads_or(bad2);

    __shared__ float red[TPB];
    float ca = 0.f, sa = 0.f, nv = 0.f;
    for (int c = tid; c < C; c += TPB) {
        float n = g.cls_n[c];
        if (n > 0.f) {
            nv += 1.f;
            float nm = fmaxf(n, 1.f);
            ca += (1.0f / sqrtf(n + 1e-6f)) * (g.cls_sum[c] / nm);
            sa += g.sep_sum[c] / nm;
        }
    }
    float sn = 0.f;
    for (int d = tid; d < D; d += TPB) { float v = g.svec[d]; sn += v * v; }
    float vc = 0.f;
    for (int t = tid; t < T; t += TPB) {
        int v = byte_mode ? (int)mask[t] : ((const int*)mask)[t];
        vc += (v != 0) ? 1.f : 0.f;
    }

    float vals[5] = {ca, sa, nv, sn, vc};
    #pragma unroll
    for (int k = 0; k < 5; k++) {
        red[tid] = vals[k];
        __syncthreads();
        for (int s = TPB >> 1; s; s >>= 1) {
            if (tid < s) red[tid] += red[tid + s];
            __syncthreads();
        }
        vals[k] = red[0];
        __syncthreads();
    }

    if (tid == 0) {
        float nvalid  = fmaxf(vals[2], 1.f);
        float cluster = vals[0] / nvalid * CLST_SCALE;
        float sep     = vals[1] / nvalid * SEP_SCALE;
        float divl    = g.div_sum / fmaxf(g.ndv, 1.f) * DIV_SCALE;
        float V       = vals[4];
        float nvp     = fmaxf(V * V - V, 1.f);
        float contr   = (vals[3] - g.diag) / nvp * CONTRASTIVE_SCALE;
        out[0] = cluster;
        out[1] = sep;
        out[2] = divl;
        out[3] = contr;
        out[4] = cluster + sep + divl + contr;
    }
}

extern "C" void kernel_launch(void* const* d_in, const int* in_sizes, int n_in,
                              void* d_out, int out_size) {
    const float* sims   = (const float*)d_in[0];
    const int*   labels = (const int*)  d_in[1];
    const float* protos = (const float*)d_in[2];
    const int*   pidx   = (const int*)  d_in[3];
    const unsigned char* mask = (const unsigned char*)d_in[4];

    const int B = in_sizes[1];
    const int C = in_sizes[3] / 2;
    const int T = in_sizes[4];
    const int D = in_sizes[2] / T;
    const int P = in_sizes[0] / (B * C);
    float* out = (float*)d_out;

    void* gp = nullptr;
    cudaGetSymbolAddress(&gp, g);
    cudaMemsetAsync(gp, 0, sizeof(Scratch), 0);

    const int CP = C * P;
    // fast path: vectorizable row fitting 8 float4/lane, window fits 16 lanes
    const int fast_ok = (((CP & 3) == 0) && (CP <= 1024) && (P <= 13)) ? 1 : 0;

    // one persistent wave of min blocks at 6 blocks/SM
    const int NMIN = 148 * 6;
    fused_kernel<<<C + NMIN, TPB, 0>>>(sims, labels, protos, pidx, mask,
                                       out, B, C, P, T, D, NMIN, fast_ok);
}